// round 14
// baseline (speedup 1.0000x reference)
#include <cuda_runtime.h>

// ---------------------------------------------------------------------------
// HEAQNetwork: 4-qubit, 3-layer ansatz, batch = 1M. One thread per element.
//
// Structure of the verified round-12 kernel (tan-form gates, observable-folded
// final CNOT chain, lightcone-pruned {2,3} tail, factored layer 0/1, layer-2
// q0 gates pulled into observables, closed-form E/g builds, fused FFMA
// measurement), plus epilogue constant folding (0.5*w_output in smem,
// rcp-based output scaling).
//
// Qubit q maps to bit (3-q) of the amplitude index.
// ---------------------------------------------------------------------------

#define NQ 4
#define QBIT(q) (1 << (3 - (q)))

// RX tan-form: [[1, -i t],[-i t, 1]] — 1 FFMA per scalar output.
template <int Q>
__device__ __forceinline__ void apply_rx_t(float sr[16], float si[16], float t) {
#pragma unroll
    for (int i = 0; i < 16; i++) {
        if (i & QBIT(Q)) continue;
        const int j = i | QBIT(Q);
        float a0r = sr[i], a0i = si[i], a1r = sr[j], a1i = si[j];
        sr[i] = fmaf( t, a1i, a0r);
        si[i] = fmaf(-t, a1r, a0i);
        sr[j] = fmaf( t, a0i, a1r);
        si[j] = fmaf(-t, a0r, a1i);
    }
}

// RY tan-form: [[1, -t],[t, 1]]
template <int Q>
__device__ __forceinline__ void apply_ry_t(float sr[16], float si[16], float t) {
#pragma unroll
    for (int i = 0; i < 16; i++) {
        if (i & QBIT(Q)) continue;
        const int j = i | QBIT(Q);
        float a0r = sr[i], a0i = si[i], a1r = sr[j], a1i = si[j];
        sr[i] = fmaf(-t, a1r, a0r);
        si[i] = fmaf(-t, a1i, a0i);
        sr[j] = fmaf( t, a0r, a1r);
        si[j] = fmaf( t, a0i, a1i);
    }
}

template <int C, int T>
__device__ __forceinline__ void apply_cnot(float sr[16], float si[16]) {
#pragma unroll
    for (int i = 0; i < 16; i++) {
        if (!(i & QBIT(C))) continue;
        if (i & QBIT(T)) continue;
        const int j = i | QBIT(T);
        float t;
        t = sr[i]; sr[i] = sr[j]; sr[j] = t;
        t = si[i]; si[i] = si[j]; si[j] = t;
    }
}

__device__ __forceinline__ void cmul(float& or_, float& oi_,
                                     float ar, float ai, float br, float bi) {
    or_ = fmaf(-ai, bi, ar * br);
    oi_ = fmaf( ai, br, ar * bi);
}

__global__ void __launch_bounds__(256)
qsim_kernel(const float4* __restrict__ x4,
            const float* __restrict__ w_input,
            const float* __restrict__ weights,
            const float* __restrict__ w_output,
            float2* __restrict__ out2,
            int B) {
    // Shared constants: tan(w/2) of RY weights; full-angle cos/sin of w8 for
    // the layer-2 q0 observable pullback; pre-halved output weights.
    __shared__ float s_tw[12];
    __shared__ float s_c8, s_2c8, s_n2s8;
    __shared__ float s_wo0h, s_wo1h;
    if (threadIdx.x < 12) {
        float sc, cc;
        sincosf(0.5f * weights[threadIdx.x], &sc, &cc);
        s_tw[threadIdx.x] = __fdividef(sc, cc);
        if (threadIdx.x == 8) {
            float cfull = cc * cc - sc * sc;   // cos(w8)
            float sfull = 2.0f * sc * cc;      // sin(w8)
            s_c8 = cfull; s_2c8 = 2.0f * cfull; s_n2s8 = -2.0f * sfull;
        }
    } else if (threadIdx.x == 12) {
        s_wo0h = 0.5f * w_output[0];
        s_wo1h = 0.5f * w_output[1];
    }
    __syncthreads();

    int b = blockIdx.x * blockDim.x + threadIdx.x;
    if (b >= B) return;

    const float4 xv = x4[b];
    float t0 = xv.x * __ldg(&w_input[0]);
    float t1 = xv.y * __ldg(&w_input[1]);
    float t2 = xv.z * __ldg(&w_input[2]);
    float t3 = xv.w * __ldg(&w_input[3]);

    // u = tan(atan(t)/2) = t / (1 + sqrt(1+t^2)); rsq0 = cos(atan t0) reused.
    float u0, u1, u2, u3, rsq0;
    {
        float d0 = fmaf(t0, t0, 1.0f); float r0 = rsqrtf(d0); rsq0 = r0;
        u0 = __fdividef(t0, fmaf(d0, r0, 1.0f));
        float d1 = fmaf(t1, t1, 1.0f); float r1 = rsqrtf(d1);
        u1 = __fdividef(t1, fmaf(d1, r1, 1.0f));
        float d2 = fmaf(t2, t2, 1.0f); float r2 = rsqrtf(d2);
        u2 = __fdividef(t2, fmaf(d2, r2, 1.0f));
        float d3 = fmaf(t3, t3, 1.0f); float r3 = rsqrtf(d3);
        u3 = __fdividef(t3, fmaf(d3, r3, 1.0f));
    }

    // ---- E[a0][a1] = v0[a0] * v1[a1^a0]  (layer-0 CNOT01 folded; closed form)
    // v_q = (1 + i*twq*uq,  twq - i*uq)
    const float tw0 = s_tw[0], tw1 = s_tw[1];
    const float A0 = tw0 * u0, A1 = tw1 * u1;
    float Er[2][2], Ei[2][2];
    Er[0][0] = fmaf(-A0, A1, 1.0f);        Ei[0][0] = A0 + A1;
    Er[0][1] = fmaf(A0, u1, tw1);          Ei[0][1] = fmaf(A0, tw1, -u1);
    Er[1][0] = fmaf(-u0, u1, tw0 * tw1);   Ei[1][0] = -fmaf(tw0, u1, u0 * tw1);
    Er[1][1] = fmaf(u0, A1, tw0);          Ei[1][1] = fmaf(tw0, A1, -u0);

    // ---- Layer-1 RX0 on E (tan u0):
#pragma unroll
    for (int a1 = 0; a1 < 2; a1++) {
        float e0r = Er[0][a1], e0i = Ei[0][a1];
        float e1r = Er[1][a1], e1i = Ei[1][a1];
        Er[0][a1] = fmaf( u0, e1i, e0r);
        Ei[0][a1] = fmaf(-u0, e1r, e0i);
        Er[1][a1] = fmaf( u0, e0i, e1r);
        Ei[1][a1] = fmaf(-u0, e0r, e1i);
    }
    // ---- Layer-1 RY0 on E (tan t4):
    {
        float t = s_tw[4];
#pragma unroll
        for (int a1 = 0; a1 < 2; a1++) {
            float e0r = Er[0][a1], e0i = Ei[0][a1];
            float e1r = Er[1][a1], e1i = Ei[1][a1];
            Er[0][a1] = fmaf(-t, e1r, e0r);
            Ei[0][a1] = fmaf(-t, e1i, e0i);
            Er[1][a1] = fmaf( t, e0r, e1r);
            Ei[1][a1] = fmaf( t, e0i, e1i);
        }
    }

    // ---- {2,3} layer-0: g[x][y] = v2[x]*v3[y] (closed form)
    const float tw2 = s_tw[2], tw3 = s_tw[3];
    const float A2 = tw2 * u2, A3 = tw3 * u3;
    float gr[2][2], gi[2][2];
    gr[0][0] = fmaf(-A2, A3, 1.0f);        gi[0][0] = A2 + A3;
    gr[0][1] = fmaf(A2, u3, tw3);          gi[0][1] = fmaf(A2, tw3, -u3);
    gr[1][0] = fmaf(u2, A3, tw2);          gi[1][0] = fmaf(tw2, A3, -u2);
    gr[1][1] = fmaf(-u2, u3, tw2 * tw3);   gi[1][1] = -fmaf(tw2, u3, u2 * tw3);

    // ---- Layer-1 RX2 on g (flip a2 maps (x,y)->(x^1,y^1); symmetric matrix)
    float hr[2][2], hi[2][2];
#pragma unroll
    for (int x = 0; x < 2; x++)
#pragma unroll
        for (int y = 0; y < 2; y++) {
            hr[x][y] = fmaf( u2, gi[x ^ 1][y ^ 1], gr[x][y]);
            hi[x][y] = fmaf(-u2, gr[x ^ 1][y ^ 1], gi[x][y]);
        }

    // ---- Layer-1 RY2: orientation depends on a1 -> fork. t = tw[6].
    float G0r[2][2], G0i[2][2], G1r[2][2], G1i[2][2];
    {
        float t = s_tw[6];
#pragma unroll
        for (int y = 0; y < 2; y++) {
            G0r[0][y] = fmaf(-t, hr[1][y ^ 1], hr[0][y]);
            G0i[0][y] = fmaf(-t, hi[1][y ^ 1], hi[0][y]);
            G0r[1][y] = fmaf( t, hr[0][y ^ 1], hr[1][y]);
            G0i[1][y] = fmaf( t, hi[0][y ^ 1], hi[1][y]);

            G1r[1][y] = fmaf(-t, hr[0][y ^ 1], hr[1][y]);
            G1i[1][y] = fmaf(-t, hi[0][y ^ 1], hi[1][y]);
            G1r[0][y] = fmaf( t, hr[1][y ^ 1], hr[0][y]);
            G1i[0][y] = fmaf( t, hi[1][y ^ 1], hi[0][y]);
        }
    }

    // ---- Expand: s[i] = E[a0][a1] * G_{a1}[a2^a1][a3^a2]
    float sr[16], si[16];
#pragma unroll
    for (int i = 0; i < 16; i++) {
        const int a0 = (i >> 3) & 1, a1 = (i >> 2) & 1;
        const int a2 = (i >> 1) & 1, a3 = i & 1;
        const int x = a2 ^ a1, y = a3 ^ a2;
        const float Gr = a1 ? G1r[x][y] : G0r[x][y];
        const float Gi = a1 ? G1i[x][y] : G0i[x][y];
        cmul(sr[i], si[i], Er[a0][a1], Ei[a0][a1], Gr, Gi);
    }

    // ---- Layer-1 q1 gates, layer-1 CNOTs, then layer-2 q1 gates.
    // (Layer-2 q0 gates pulled into the observables below.)
    apply_rx_t<1>(sr, si, u1);
    apply_ry_t<1>(sr, si, s_tw[5]);
    apply_cnot<0, 1>(sr, si);
    apply_cnot<1, 2>(sr, si);
    apply_rx_t<1>(sr, si, u1);
    apply_ry_t<1>(sr, si, s_tw[9]);

    // ---- Fused measurement: group probabilities (by a0,a1) and a0-cross
    // terms in one pass, all as FFMA accumulations.
    float zg0 = 0.0f, zg1 = 0.0f, zg2 = 0.0f, zg3 = 0.0f;
    float xr0 = 0.0f, xr1 = 0.0f, xi0 = 0.0f, xi1 = 0.0f;
#pragma unroll
    for (int i = 0; i < 8; i++) {
        const int j = i + 8;
        float ar = sr[i], ai = si[i], br = sr[j], bi = si[j];
        if (!(i & 4)) {
            zg0 = fmaf(ar, ar, zg0); zg0 = fmaf(ai, ai, zg0);
            zg2 = fmaf(br, br, zg2); zg2 = fmaf(bi, bi, zg2);
            xr0 = fmaf(ar, br, xr0); xr0 = fmaf(ai, bi, xr0);
            xi0 = fmaf(ar, bi, xi0); xi0 = fmaf(-ai, br, xi0);
        } else {
            zg1 = fmaf(ar, ar, zg1); zg1 = fmaf(ai, ai, zg1);
            zg3 = fmaf(br, br, zg3); zg3 = fmaf(bi, bi, zg3);
            xr1 = fmaf(ar, br, xr1); xr1 = fmaf(ai, bi, xr1);
            xi1 = fmaf(ar, bi, xi1); xi1 = fmaf(-ai, br, xi1);
        }
    }

    // ---- Observables (layer-2 q0 gates pulled back):
    //   O  = cB*c0*Z0 + cB*s0*Y0 - sB*X0        (out0)
    //   O' = O (x) Z1                            (out1)
    float p01 = zg0 + zg1, p23 = zg2 + zg3;
    float S   = p01 + p23;
    float Z0u = p01 - p23;
    float ZZu = (zg0 + zg3) - (zg1 + zg2);
    float Xu  = xr0 + xr1, XZ = xr0 - xr1;
    float Yu  = xi0 + xi1, YZ = xi0 - xi1;

    float s0 = t0 * rsq0;
    float Ac = s_c8 * rsq0;     // cB * c0
    float B2 = s_2c8 * s0;      // 2 * cB * s0
    float C2 = s_n2s8;          // -2 * sB

    float O1u = fmaf(Ac, Z0u, fmaf(B2, Yu, C2 * Xu));
    float O2u = fmaf(Ac, ZZu, fmaf(B2, YZ, C2 * XZ));

    // out = woh * (1 + O/S)  =  fmaf(O*invS, woh, woh)
    float invS = __fdividef(1.0f, S);
    float2 o;
    o.x = fmaf(O1u * invS, s_wo0h, s_wo0h);
    o.y = fmaf(O2u * invS, s_wo1h, s_wo1h);
    out2[b] = o;
}

extern "C" void kernel_launch(void* const* d_in, const int* in_sizes, int n_in,
                              void* d_out, int out_size) {
    const float* x        = (const float*)d_in[0];  // (B, 4)
    const float* w_input  = (const float*)d_in[1];  // (4,)
    const float* weights  = (const float*)d_in[2];  // (3, 4)
    const float* w_output = (const float*)d_in[3];  // (2,)
    float* out = (float*)d_out;                     // (B, 2)

    int B = in_sizes[0] / NQ;

    qsim_kernel<<<(B + 255) / 256, 256>>>(
        (const float4*)x, w_input, weights, w_output, (float2*)out, B);
}

// round 16
// speedup vs baseline: 1.1729x; 1.1729x over previous
#include <cuda_runtime.h>

// ---------------------------------------------------------------------------
// HEAQNetwork: 4-qubit, 3-layer ansatz, batch = 1M. One thread per element.
//
// Structure of the verified round-8 kernel (tan-form gates, observable-folded
// final CNOT chain, lightcone-pruned {2,3} tail, factored layer 0/1, layer-2
// q0 gates pulled into observables), plus:
//  * closed-form E and g tensor builds (no intermediate v vectors),
//  * measurement accumulated directly via FFMA (no standalone adds),
//    probs + a0-cross terms fused into one pass.
//
// Qubit q maps to bit (3-q) of the amplitude index.
// ---------------------------------------------------------------------------

#define NQ 4
#define QBIT(q) (1 << (3 - (q)))

// RX tan-form: [[1, -i t],[-i t, 1]] — 1 FFMA per scalar output.
template <int Q>
__device__ __forceinline__ void apply_rx_t(float sr[16], float si[16], float t) {
#pragma unroll
    for (int i = 0; i < 16; i++) {
        if (i & QBIT(Q)) continue;
        const int j = i | QBIT(Q);
        float a0r = sr[i], a0i = si[i], a1r = sr[j], a1i = si[j];
        sr[i] = fmaf( t, a1i, a0r);
        si[i] = fmaf(-t, a1r, a0i);
        sr[j] = fmaf( t, a0i, a1r);
        si[j] = fmaf(-t, a0r, a1i);
    }
}

// RY tan-form: [[1, -t],[t, 1]]
template <int Q>
__device__ __forceinline__ void apply_ry_t(float sr[16], float si[16], float t) {
#pragma unroll
    for (int i = 0; i < 16; i++) {
        if (i & QBIT(Q)) continue;
        const int j = i | QBIT(Q);
        float a0r = sr[i], a0i = si[i], a1r = sr[j], a1i = si[j];
        sr[i] = fmaf(-t, a1r, a0r);
        si[i] = fmaf(-t, a1i, a0i);
        sr[j] = fmaf( t, a0r, a1r);
        si[j] = fmaf( t, a0i, a1i);
    }
}

template <int C, int T>
__device__ __forceinline__ void apply_cnot(float sr[16], float si[16]) {
#pragma unroll
    for (int i = 0; i < 16; i++) {
        if (!(i & QBIT(C))) continue;
        if (i & QBIT(T)) continue;
        const int j = i | QBIT(T);
        float t;
        t = sr[i]; sr[i] = sr[j]; sr[j] = t;
        t = si[i]; si[i] = si[j]; si[j] = t;
    }
}

__device__ __forceinline__ void cmul(float& or_, float& oi_,
                                     float ar, float ai, float br, float bi) {
    or_ = fmaf(-ai, bi, ar * br);
    oi_ = fmaf( ai, br, ar * bi);
}

__global__ void __launch_bounds__(256)
qsim_kernel(const float4* __restrict__ x4,
            const float* __restrict__ w_input,
            const float* __restrict__ weights,
            const float* __restrict__ w_output,
            float2* __restrict__ out2,
            int B) {
    // tan(w/2) of RY weights; full-angle cos/sin of w8 for the layer-2 q0
    // observable pullback.
    __shared__ float s_tw[12];
    __shared__ float s_c8, s_2c8, s_n2s8;
    if (threadIdx.x < 12) {
        float sc, cc;
        sincosf(0.5f * weights[threadIdx.x], &sc, &cc);
        s_tw[threadIdx.x] = __fdividef(sc, cc);
        if (threadIdx.x == 8) {
            float cfull = cc * cc - sc * sc;   // cos(w8)
            float sfull = 2.0f * sc * cc;      // sin(w8)
            s_c8 = cfull; s_2c8 = 2.0f * cfull; s_n2s8 = -2.0f * sfull;
        }
    }
    __syncthreads();

    int b = blockIdx.x * blockDim.x + threadIdx.x;
    if (b >= B) return;

    const float4 xv = x4[b];
    float t0 = xv.x * __ldg(&w_input[0]);
    float t1 = xv.y * __ldg(&w_input[1]);
    float t2 = xv.z * __ldg(&w_input[2]);
    float t3 = xv.w * __ldg(&w_input[3]);

    // u = tan(atan(t)/2) = t / (1 + sqrt(1+t^2)); rsq0 = cos(atan t0) reused.
    float u0, u1, u2, u3, rsq0;
    {
        float d0 = fmaf(t0, t0, 1.0f); float r0 = rsqrtf(d0); rsq0 = r0;
        u0 = __fdividef(t0, fmaf(d0, r0, 1.0f));
        float d1 = fmaf(t1, t1, 1.0f); float r1 = rsqrtf(d1);
        u1 = __fdividef(t1, fmaf(d1, r1, 1.0f));
        float d2 = fmaf(t2, t2, 1.0f); float r2 = rsqrtf(d2);
        u2 = __fdividef(t2, fmaf(d2, r2, 1.0f));
        float d3 = fmaf(t3, t3, 1.0f); float r3 = rsqrtf(d3);
        u3 = __fdividef(t3, fmaf(d3, r3, 1.0f));
    }

    // ---- E[a0][a1] = v0[a0] * v1[a1^a0]  (layer-0 CNOT01 folded; closed form)
    // v_q = (1 + i*twq*uq,  twq - i*uq)
    const float tw0 = s_tw[0], tw1 = s_tw[1];
    const float A0 = tw0 * u0, A1 = tw1 * u1;
    float Er[2][2], Ei[2][2];
    Er[0][0] = fmaf(-A0, A1, 1.0f);        Ei[0][0] = A0 + A1;
    Er[0][1] = fmaf(A0, u1, tw1);          Ei[0][1] = fmaf(A0, tw1, -u1);
    Er[1][0] = fmaf(-u0, u1, tw0 * tw1);   Ei[1][0] = -fmaf(tw0, u1, u0 * tw1);
    Er[1][1] = fmaf(u0, A1, tw0);          Ei[1][1] = fmaf(tw0, A1, -u0);

    // ---- Layer-1 RX0 on E (tan u0):
#pragma unroll
    for (int a1 = 0; a1 < 2; a1++) {
        float e0r = Er[0][a1], e0i = Ei[0][a1];
        float e1r = Er[1][a1], e1i = Ei[1][a1];
        Er[0][a1] = fmaf( u0, e1i, e0r);
        Ei[0][a1] = fmaf(-u0, e1r, e0i);
        Er[1][a1] = fmaf( u0, e0i, e1r);
        Ei[1][a1] = fmaf(-u0, e0r, e1i);
    }
    // ---- Layer-1 RY0 on E (tan t4):
    {
        float t = s_tw[4];
#pragma unroll
        for (int a1 = 0; a1 < 2; a1++) {
            float e0r = Er[0][a1], e0i = Ei[0][a1];
            float e1r = Er[1][a1], e1i = Ei[1][a1];
            Er[0][a1] = fmaf(-t, e1r, e0r);
            Ei[0][a1] = fmaf(-t, e1i, e0i);
            Er[1][a1] = fmaf( t, e0r, e1r);
            Ei[1][a1] = fmaf( t, e0i, e1i);
        }
    }

    // ---- {2,3} layer-0: g[x][y] = v2[x]*v3[y] (closed form)
    const float tw2 = s_tw[2], tw3 = s_tw[3];
    const float A2 = tw2 * u2, A3 = tw3 * u3;
    float gr[2][2], gi[2][2];
    gr[0][0] = fmaf(-A2, A3, 1.0f);        gi[0][0] = A2 + A3;
    gr[0][1] = fmaf(A2, u3, tw3);          gi[0][1] = fmaf(A2, tw3, -u3);
    gr[1][0] = fmaf(u2, A3, tw2);          gi[1][0] = fmaf(tw2, A3, -u2);
    gr[1][1] = fmaf(-u2, u3, tw2 * tw3);   gi[1][1] = -fmaf(tw2, u3, u2 * tw3);

    // ---- Layer-1 RX2 on g (flip a2 maps (x,y)->(x^1,y^1); symmetric matrix)
    float hr[2][2], hi[2][2];
#pragma unroll
    for (int x = 0; x < 2; x++)
#pragma unroll
        for (int y = 0; y < 2; y++) {
            hr[x][y] = fmaf( u2, gi[x ^ 1][y ^ 1], gr[x][y]);
            hi[x][y] = fmaf(-u2, gr[x ^ 1][y ^ 1], gi[x][y]);
        }

    // ---- Layer-1 RY2: orientation depends on a1 -> fork. t = tw[6].
    float G0r[2][2], G0i[2][2], G1r[2][2], G1i[2][2];
    {
        float t = s_tw[6];
#pragma unroll
        for (int y = 0; y < 2; y++) {
            G0r[0][y] = fmaf(-t, hr[1][y ^ 1], hr[0][y]);
            G0i[0][y] = fmaf(-t, hi[1][y ^ 1], hi[0][y]);
            G0r[1][y] = fmaf( t, hr[0][y ^ 1], hr[1][y]);
            G0i[1][y] = fmaf( t, hi[0][y ^ 1], hi[1][y]);

            G1r[1][y] = fmaf(-t, hr[0][y ^ 1], hr[1][y]);
            G1i[1][y] = fmaf(-t, hi[0][y ^ 1], hi[1][y]);
            G1r[0][y] = fmaf( t, hr[1][y ^ 1], hr[0][y]);
            G1i[0][y] = fmaf( t, hi[1][y ^ 1], hi[0][y]);
        }
    }

    // ---- Expand: s[i] = E[a0][a1] * G_{a1}[a2^a1][a3^a2]
    float sr[16], si[16];
#pragma unroll
    for (int i = 0; i < 16; i++) {
        const int a0 = (i >> 3) & 1, a1 = (i >> 2) & 1;
        const int a2 = (i >> 1) & 1, a3 = i & 1;
        const int x = a2 ^ a1, y = a3 ^ a2;
        const float Gr = a1 ? G1r[x][y] : G0r[x][y];
        const float Gi = a1 ? G1i[x][y] : G0i[x][y];
        cmul(sr[i], si[i], Er[a0][a1], Ei[a0][a1], Gr, Gi);
    }

    // ---- Layer-1 q1 gates, layer-1 CNOTs, then layer-2 q1 gates.
    // (Layer-2 q0 gates pulled into the observables below.)
    apply_rx_t<1>(sr, si, u1);
    apply_ry_t<1>(sr, si, s_tw[5]);
    apply_cnot<0, 1>(sr, si);
    apply_cnot<1, 2>(sr, si);
    apply_rx_t<1>(sr, si, u1);
    apply_ry_t<1>(sr, si, s_tw[9]);

    // ---- Fused measurement: group probabilities (by a0,a1) and a0-cross
    // terms in one pass, all as FFMA accumulations.
    float zg0 = 0.0f, zg1 = 0.0f, zg2 = 0.0f, zg3 = 0.0f;
    float xr0 = 0.0f, xr1 = 0.0f, xi0 = 0.0f, xi1 = 0.0f;
#pragma unroll
    for (int i = 0; i < 8; i++) {
        const int j = i + 8;
        float ar = sr[i], ai = si[i], br = sr[j], bi = si[j];
        if (!(i & 4)) {
            zg0 = fmaf(ar, ar, zg0); zg0 = fmaf(ai, ai, zg0);
            zg2 = fmaf(br, br, zg2); zg2 = fmaf(bi, bi, zg2);
            xr0 = fmaf(ar, br, xr0); xr0 = fmaf(ai, bi, xr0);
            xi0 = fmaf(ar, bi, xi0); xi0 = fmaf(-ai, br, xi0);
        } else {
            zg1 = fmaf(ar, ar, zg1); zg1 = fmaf(ai, ai, zg1);
            zg3 = fmaf(br, br, zg3); zg3 = fmaf(bi, bi, zg3);
            xr1 = fmaf(ar, br, xr1); xr1 = fmaf(ai, bi, xr1);
            xi1 = fmaf(ar, bi, xi1); xi1 = fmaf(-ai, br, xi1);
        }
    }

    // ---- Observables (layer-2 q0 gates pulled back):
    //   O  = cB*c0*Z0 + cB*s0*Y0 - sB*X0        (out0)
    //   O' = O (x) Z1                            (out1)
    float p01 = zg0 + zg1, p23 = zg2 + zg3;
    float S   = p01 + p23;
    float Z0u = p01 - p23;
    float ZZu = (zg0 + zg3) - (zg1 + zg2);
    float Xu  = xr0 + xr1, XZ = xr0 - xr1;
    float Yu  = xi0 + xi1, YZ = xi0 - xi1;

    float s0 = t0 * rsq0;
    float Ac = s_c8 * rsq0;     // cB * c0
    float B2 = s_2c8 * s0;      // 2 * cB * s0
    float C2 = s_n2s8;          // -2 * sB

    float O1u = fmaf(Ac, Z0u, fmaf(B2, Yu, C2 * Xu));
    float O2u = fmaf(Ac, ZZu, fmaf(B2, YZ, C2 * XZ));

    float h = 0.5f * __fdividef(1.0f, S);
    float2 o;
    o.x = __ldg(&w_output[0]) * ((S + O1u) * h);
    o.y = __ldg(&w_output[1]) * ((S + O2u) * h);
    out2[b] = o;
}

extern "C" void kernel_launch(void* const* d_in, const int* in_sizes, int n_in,
                              void* d_out, int out_size) {
    const float* x        = (const float*)d_in[0];  // (B, 4)
    const float* w_input  = (const float*)d_in[1];  // (4,)
    const float* weights  = (const float*)d_in[2];  // (3, 4)
    const float* w_output = (const float*)d_in[3];  // (2,)
    float* out = (float*)d_out;                     // (B, 2)

    int B = in_sizes[0] / NQ;

    qsim_kernel<<<(B + 255) / 256, 256>>>(
        (const float4*)x, w_input, weights, w_output, (float2*)out, B);
}